// round 1
// baseline (speedup 1.0000x reference)
#include <cuda_runtime.h>

#define D    2048
#define E    16
#define R    16
#define QO   2048
#define VO   512
#define NTOK 4096
#define SCALE 2.0f
#define TM   32
#define MAXTILES (NTOK / TM + E)   // 144: upper bound on sum_e ceil(cnt_e/TM)

// ---------------- scratch (device globals; no allocation) ----------------
__device__ int   g_top_idx[NTOK * 2];
__device__ float g_top_w[NTOK * 2];
__device__ int   g_cnt[2][E];
__device__ int   g_off[2][E + 1];
__device__ int   g_fill[2][E];
__device__ int   g_tileoff[2][E + 1];
__device__ int   g_perm[2][NTOK];
__device__ float g_lowq[2][NTOK][R];
__device__ float g_lowv[2][NTOK][R];

// ---------------- init: zero per-expert counters ----------------
__global__ void k_init() {
    int i = threadIdx.x;
    if (i < E) { g_cnt[0][i] = 0; g_cnt[1][i] = 0; }
}

// ---------------- router: logits, softmax, top-2, renorm weights ----------------
// 1 block per token, 256 threads = 8 warps, each warp computes 2 expert dots.
__global__ void __launch_bounds__(256) k_router(const float* __restrict__ h,
                                                const float* __restrict__ W) {
    int t = blockIdx.x;
    int warp = threadIdx.x >> 5, lane = threadIdx.x & 31;
    const float4* h4 = (const float4*)(h + (size_t)t * D);
    int e0 = warp * 2;
    const float4* wa = (const float4*)(W + (size_t)e0 * D);
    const float4* wb = (const float4*)(W + (size_t)(e0 + 1) * D);
    float s0 = 0.f, s1 = 0.f;
    #pragma unroll 4
    for (int i = lane; i < D / 4; i += 32) {
        float4 hv = h4[i], a = wa[i], b = wb[i];
        s0 += hv.x * a.x + hv.y * a.y + hv.z * a.z + hv.w * a.w;
        s1 += hv.x * b.x + hv.y * b.y + hv.z * b.z + hv.w * b.w;
    }
    #pragma unroll
    for (int o = 16; o > 0; o >>= 1) {
        s0 += __shfl_xor_sync(0xffffffffu, s0, o);
        s1 += __shfl_xor_sync(0xffffffffu, s1, o);
    }
    __shared__ float lg[E];
    if (lane == 0) { lg[e0] = s0; lg[e0 + 1] = s1; }
    __syncthreads();
    if (threadIdx.x == 0) {
        float m = lg[0];
        #pragma unroll
        for (int i = 1; i < E; i++) m = fmaxf(m, lg[i]);
        float ex[E], Z = 0.f;
        #pragma unroll
        for (int i = 0; i < E; i++) { ex[i] = expf(lg[i] - m); Z += ex[i]; }
        int i0 = 0;
        #pragma unroll
        for (int i = 1; i < E; i++) if (lg[i] > lg[i0]) i0 = i;
        int i1 = (i0 == 0) ? 1 : 0;
        #pragma unroll
        for (int i = 0; i < E; i++) if (i != i0 && lg[i] > lg[i1]) i1 = i;
        float p0 = ex[i0] / Z, p1 = ex[i1] / Z;
        float dn = p0 + p1 + 1e-20f;
        g_top_idx[t * 2]     = i0;
        g_top_idx[t * 2 + 1] = i1;
        g_top_w[t * 2]       = SCALE * p0 / dn;
        g_top_w[t * 2 + 1]   = SCALE * p1 / dn;
    }
}

// ---------------- count: warp-aggregated histogram over (k, expert) ----------------
__global__ void k_count(int n) {
    int t = blockIdx.x * blockDim.x + threadIdx.x;
    int lane = threadIdx.x & 31;
    #pragma unroll
    for (int k = 0; k < 2; k++) {
        int e = (t < n) ? g_top_idx[t * 2 + k] : -1;
        unsigned mask = __match_any_sync(0xffffffffu, e);
        int leader = __ffs(mask) - 1;
        if (e >= 0 && lane == leader) atomicAdd(&g_cnt[k][e], __popc(mask));
    }
}

// ---------------- scan: token offsets + tile offsets (trivial, 1 thread) ----------------
__global__ void k_scan() {
    if (threadIdx.x == 0) {
        #pragma unroll
        for (int k = 0; k < 2; k++) {
            int acc = 0, tacc = 0;
            for (int e = 0; e < E; e++) {
                g_off[k][e] = acc; g_fill[k][e] = acc; g_tileoff[k][e] = tacc;
                int c = g_cnt[k][e];
                acc += c; tacc += (c + TM - 1) / TM;
            }
            g_off[k][E] = acc; g_tileoff[k][E] = tacc;
        }
    }
}

// ---------------- scatter: per-(k,expert) sorted token lists ----------------
__global__ void k_scatter(int n) {
    int t = blockIdx.x * blockDim.x + threadIdx.x;
    int lane = threadIdx.x & 31;
    #pragma unroll
    for (int k = 0; k < 2; k++) {
        int e = (t < n) ? g_top_idx[t * 2 + k] : -1;
        unsigned mask = __match_any_sync(0xffffffffu, e);
        int leader = __ffs(mask) - 1;
        int base = 0;
        if (e >= 0 && lane == leader) base = atomicAdd(&g_fill[k][e], __popc(mask));
        base = __shfl_sync(0xffffffffu, base, leader);
        int rank = __popc(mask & ((1u << lane) - 1u));
        if (e >= 0) g_perm[k][base + rank] = t;
    }
}

// ---------------- low projection: low[tok, 32] = h[tok,:] @ [Aq(e) | Av(e)], * weight ----
// grid (MAXTILES, 2=k). 256 threads. TM=32 tokens x 32 outputs, K=2048 in chunks of 64.
__global__ void __launch_bounds__(256) k_low(const float* __restrict__ h,
                                             const float* __restrict__ qa,
                                             const float* __restrict__ va) {
    int k = blockIdx.y;
    int tileId = blockIdx.x;
    if (tileId >= g_tileoff[k][E]) return;
    int e = 0;
    #pragma unroll
    for (int i = 1; i < E; i++) if (tileId >= g_tileoff[k][i]) e = i;
    int tb = tileId - g_tileoff[k][e];
    int base = g_off[k][e] + tb * TM;
    int nrows = min(TM, g_off[k][e + 1] - base);

    __shared__ float hs[TM][68];       // pad 68: (4*row + d) % 32 conflict-free
    __shared__ float as[64][32];       // [d-chunk][0..15 q | 16..31 v]
    __shared__ int   toks[TM];

    int tid = threadIdx.x;
    if (tid < TM) toks[tid] = g_perm[k][base + ((tid < nrows) ? tid : 0)];
    __syncthreads();

    int myrow = tid >> 3;        // 0..31 token
    int sub   = tid & 7;         // 0..7 -> 4 output cols each
    float acc[4] = {0.f, 0.f, 0.f, 0.f};

    const float* Aq = qa + (size_t)e * D * R;
    const float* Av = va + (size_t)e * D * R;

    for (int kc = 0; kc < D; kc += 64) {
        // A chunk: 64 rows x 16 floats each for q and v (1 float4 per thread each)
        {
            int row = tid >> 2, quad = tid & 3;   // tid 0..255 -> rows 0..63
            *(float4*)&as[row][quad * 4]      = *(const float4*)(Aq + (size_t)(kc + row) * R + quad * 4);
            *(float4*)&as[row][16 + quad * 4] = *(const float4*)(Av + (size_t)(kc + row) * R + quad * 4);
        }
        // h chunk: 32 tokens x 64 floats (2 float4 per thread)
        #pragma unroll
        for (int i = 0; i < 2; i++) {
            int idx = tid + 256 * i;             // 0..511
            int row = idx >> 4, c4 = idx & 15;
            float4 hv = *(const float4*)(h + (size_t)toks[row] * D + kc + c4 * 4);
            *(float4*)&hs[row][c4 * 4] = hv;
        }
        __syncthreads();
        #pragma unroll 16
        for (int dd = 0; dd < 64; dd++) {
            float hv = hs[myrow][dd];
            float4 a4 = *(const float4*)&as[dd][sub * 4];
            acc[0] += hv * a4.x;
            acc[1] += hv * a4.y;
            acc[2] += hv * a4.z;
            acc[3] += hv * a4.w;
        }
        __syncthreads();
    }

    if (myrow < nrows) {
        int t = toks[myrow];
        float w = g_top_w[t * 2 + k];
        int pos = base + myrow;
        #pragma unroll
        for (int j = 0; j < 4; j++) {
            int c = sub * 4 + j;
            float v = acc[j] * w;
            if (c < 16) g_lowq[k][pos][c]      = v;
            else        g_lowv[k][pos][c - 16] = v;
        }
    }
}

// ---------------- delta: out[tok, cols] (+)= low[tok,:] @ B_e[:, cols] ----------------
// grid (MAXTILES, 20): y 0..15 -> q col-chunks of 128, y 16..19 -> v col-chunks.
// k passed as param; k=0 plain store, k=1 read-add-store (unique writer per row per pass).
__global__ void __launch_bounds__(256) k_delta(int k,
                                               const float* __restrict__ qb,
                                               const float* __restrict__ vb,
                                               float* __restrict__ out) {
    int tileId = blockIdx.x;
    if (tileId >= g_tileoff[k][E]) return;
    int e = 0;
    #pragma unroll
    for (int i = 1; i < E; i++) if (tileId >= g_tileoff[k][i]) e = i;
    int tb = tileId - g_tileoff[k][e];
    int base = g_off[k][e] + tb * TM;
    int nrows = min(TM, g_off[k][e + 1] - base);

    int cc = blockIdx.y;
    const float* B; float* O; int ldO, ldB;
    const float (*low)[R];
    if (cc < 16) {
        int colBase = cc * 128;
        B = qb + (size_t)e * R * QO + colBase;
        O = out + colBase; ldO = QO; ldB = QO;
        low = g_lowq[k];
    } else {
        int colBase = (cc - 16) * 128;
        B = vb + (size_t)e * R * VO + colBase;
        O = out + (size_t)NTOK * QO + colBase; ldO = VO; ldB = VO;
        low = g_lowv[k];
    }

    __shared__ float Bs[R][128];
    __shared__ float ls[TM][17];     // pad 17 -> conflict-free
    __shared__ int   toks[TM];

    int tid = threadIdx.x;
    #pragma unroll
    for (int i = 0; i < 2; i++) {
        int idx = tid + 256 * i;       // 0..511 -> 16 rows x 32 float4
        int r = idx >> 5, q4 = idx & 31;
        *(float4*)&Bs[r][q4 * 4] = *(const float4*)(B + (size_t)r * ldB + q4 * 4);
    }
    #pragma unroll
    for (int i = 0; i < 2; i++) {
        int idx = tid + 256 * i;       // 0..511 -> 32 rows x 16
        int row = idx >> 4, r = idx & 15;
        ls[row][r] = low[base + ((row < nrows) ? row : 0)][r];
    }
    if (tid < TM) toks[tid] = (tid < nrows) ? g_perm[k][base + tid] : 0;
    __syncthreads();

    int tx = tid & 31, ty = tid >> 5;   // ty = warp id: 4 tokens each; tx: 4 cols each
    float acc[4][4];
    #pragma unroll
    for (int i = 0; i < 4; i++)
        #pragma unroll
        for (int j = 0; j < 4; j++) acc[i][j] = 0.f;

    #pragma unroll
    for (int r = 0; r < R; r++) {
        float4 b4 = *(const float4*)&Bs[r][tx * 4];
        #pragma unroll
        for (int i = 0; i < 4; i++) {
            float a = ls[ty * 4 + i][r];   // broadcast within warp
            acc[i][0] += a * b4.x;
            acc[i][1] += a * b4.y;
            acc[i][2] += a * b4.z;
            acc[i][3] += a * b4.w;
        }
    }

    #pragma unroll
    for (int i = 0; i < 4; i++) {
        int row = ty * 4 + i;
        if (row < nrows) {
            float* p = O + (size_t)toks[row] * ldO + tx * 4;
            float4 v = make_float4(acc[i][0], acc[i][1], acc[i][2], acc[i][3]);
            if (k == 1) {
                float4 old = *(const float4*)p;
                v.x += old.x; v.y += old.y; v.z += old.z; v.w += old.w;
            }
            *(float4*)p = v;
        }
    }
}

// ---------------- launcher ----------------
extern "C" void kernel_launch(void* const* d_in, const int* in_sizes, int n_in,
                              void* d_out, int out_size) {
    const float* h  = (const float*)d_in[0];
    const float* W  = (const float*)d_in[1];
    const float* qa = (const float*)d_in[2];
    const float* qb = (const float*)d_in[3];
    const float* va = (const float*)d_in[4];
    const float* vb = (const float*)d_in[5];
    float* out = (float*)d_out;
    int n = in_sizes[0] / D;   // 4096

    k_init<<<1, 32>>>();
    k_router<<<n, 256>>>(h, W);
    k_count<<<(n + 255) / 256, 256>>>(n);
    k_scan<<<1, 32>>>();
    k_scatter<<<(n + 255) / 256, 256>>>(n);
    dim3 gb(MAXTILES, 2);
    k_low<<<gb, 256>>>(h, qa, va);
    dim3 gc(MAXTILES, 20);
    k_delta<<<gc, 256>>>(0, qb, vb, out);
    k_delta<<<gc, 256>>>(1, qb, vb, out);
}